// round 1
// baseline (speedup 1.0000x reference)
#include <cuda_runtime.h>
#include <cuda_bf16.h>
#include <cstdint>

// Problem constants
constexpr int B = 4;
constexpr int S = 4096;
constexpr int D = 256;
constexpr int L = 8921;

constexpr int LT1 = 128;               // K1 l-tile
constexpr int ST1 = 128;               // K1 s-tile
constexpr int KC  = 16;                // K1 k-chunk
constexpr int NLT = (L + LT1 - 1) / LT1;   // 70
constexpr int NST = S / ST1;               // 32

constexpr int LT3 = 64;                // K3 l-tile
constexpr int SC  = 32;                // K3 s-chunk
constexpr int NLT3 = (L + LT3 - 1) / LT3;  // 140

// Scratch (no cudaMalloc allowed): partial stats per (b,l,s-tile) + final stats
__device__ float g_pm[(size_t)B * L * NST];
__device__ float g_pz[(size_t)B * L * NST];
__device__ float g_M [(size_t)B * L];
__device__ float g_Zi[(size_t)B * L];

// ---------------------------------------------------------------------------
// K1: scores[b,l,s] = sum_d U[l,d]*x[b,s,d]; write raw scores into alpha buf,
//     emit per-(l, s-tile) partial max and partial sum(exp(s - localmax)).
// ---------------------------------------------------------------------------
__global__ void __launch_bounds__(256) k_scores(
    const float* __restrict__ x, const float* __restrict__ U,
    float* __restrict__ sc /* alpha buffer used as scratch */)
{
    const int b  = blockIdx.z;
    const int lt = blockIdx.y;
    const int st = blockIdx.x;
    const int l0 = lt * LT1;
    const int s0 = st * ST1;

    const int tid = threadIdx.x;
    const int tx  = tid & 15;   // s micro-tile
    const int ty  = tid >> 4;   // l micro-tile

    __shared__ __align__(16) float Us[KC][LT1];
    __shared__ __align__(16) float Xs[KC][ST1];

    float acc[8][8];
#pragma unroll
    for (int i = 0; i < 8; i++)
#pragma unroll
        for (int j = 0; j < 8; j++) acc[i][j] = 0.f;

    const float* xb = x + (size_t)b * S * D;

    for (int kc = 0; kc < D; kc += KC) {
#pragma unroll
        for (int t = 0; t < 8; t++) {
            int idx = tid + t * 256;       // 0..2047
            int r = idx >> 4;
            int c = idx & 15;
            int l = l0 + r;
            Us[c][r] = (l < L) ? U[(size_t)l * D + kc + c] : 0.f;
            Xs[c][r] = xb[(size_t)(s0 + r) * D + kc + c];
        }
        __syncthreads();

#pragma unroll
        for (int k = 0; k < KC; k++) {
            float4 a0 = *(const float4*)&Us[k][ty * 8];
            float4 a1 = *(const float4*)&Us[k][ty * 8 + 4];
            float4 b0 = *(const float4*)&Xs[k][tx * 8];
            float4 b1 = *(const float4*)&Xs[k][tx * 8 + 4];
            float av[8] = {a0.x, a0.y, a0.z, a0.w, a1.x, a1.y, a1.z, a1.w};
            float bv[8] = {b0.x, b0.y, b0.z, b0.w, b1.x, b1.y, b1.z, b1.w};
#pragma unroll
            for (int i = 0; i < 8; i++)
#pragma unroll
                for (int j = 0; j < 8; j++) acc[i][j] = fmaf(av[i], bv[j], acc[i][j]);
        }
        __syncthreads();
    }

    // Epilogue: write raw scores + partial row stats (max, sumexp at local max)
#pragma unroll
    for (int i = 0; i < 8; i++) {
        int l = l0 + ty * 8 + i;
        bool valid = (l < L);

        if (valid) {
            float4* dst = (float4*)(sc + ((size_t)b * L + l) * S + s0 + tx * 8);
            dst[0] = make_float4(acc[i][0], acc[i][1], acc[i][2], acc[i][3]);
            dst[1] = make_float4(acc[i][4], acc[i][5], acc[i][6], acc[i][7]);
        }

        float m = acc[i][0];
#pragma unroll
        for (int j = 1; j < 8; j++) m = fmaxf(m, acc[i][j]);
#pragma unroll
        for (int o = 1; o < 16; o <<= 1)
            m = fmaxf(m, __shfl_xor_sync(0xffffffffu, m, o));

        float z = 0.f;
#pragma unroll
        for (int j = 0; j < 8; j++) z += __expf(acc[i][j] - m);
#pragma unroll
        for (int o = 1; o < 16; o <<= 1)
            z += __shfl_xor_sync(0xffffffffu, z, o);

        if (valid && tx == 0) {
            size_t pidx = ((size_t)b * L + l) * NST + st;
            g_pm[pidx] = m;
            g_pz[pidx] = z;
        }
    }
}

// ---------------------------------------------------------------------------
// K2: reduce 32 partials per (b,l) -> global max M and 1/Z
// ---------------------------------------------------------------------------
__global__ void k_reduce()
{
    int idx = blockIdx.x * blockDim.x + threadIdx.x;
    if (idx >= B * L) return;
    const float* pm = g_pm + (size_t)idx * NST;
    const float* pz = g_pz + (size_t)idx * NST;
    float M = -3.4e38f;
#pragma unroll
    for (int t = 0; t < NST; t++) M = fmaxf(M, pm[t]);
    float Z = 0.f;
#pragma unroll
    for (int t = 0; t < NST; t++) Z += pz[t] * __expf(pm[t] - M);
    g_M[idx]  = M;
    g_Zi[idx] = 1.0f / Z;
}

// ---------------------------------------------------------------------------
// K3: alpha = exp(score - M) * Zi written in place; out[b,l,:] += alpha * x
// ---------------------------------------------------------------------------
__global__ void __launch_bounds__(256) k_out(
    const float* __restrict__ x,
    float* __restrict__ alpha,
    float* __restrict__ out)
{
    const int b  = blockIdx.y;
    const int lt = blockIdx.x;
    const int l0 = lt * LT3;

    const int tid = threadIdx.x;
    const int tx  = tid & 15;   // d micro-tile (16 floats)
    const int ty  = tid >> 4;   // l micro-tile (4 rows)

    __shared__ __align__(16) float As[LT3][SC];   // alpha chunk, 8 KB
    __shared__ __align__(16) float Xs[SC][D];     // x chunk, 32 KB
    __shared__ float Ms[LT3];
    __shared__ float Zs[LT3];

    if (tid < LT3) {
        int l = l0 + tid;
        bool v = (l < L);
        Ms[tid] = v ? g_M [(size_t)b * L + l] : 0.f;
        Zs[tid] = v ? g_Zi[(size_t)b * L + l] : 0.f;
    }
    __syncthreads();

    float acc[4][16];
#pragma unroll
    for (int i = 0; i < 4; i++)
#pragma unroll
        for (int k = 0; k < 16; k++) acc[i][k] = 0.f;

    const float* xb = x + (size_t)b * S * D;

    for (int s0 = 0; s0 < S; s0 += SC) {
        // scores -> alpha (in place) + stage into SMEM
#pragma unroll
        for (int t = 0; t < 8; t++) {
            int idx = tid + t * 256;     // 0..2047 (64*32)
            int r = idx >> 5;
            int c = idx & 31;
            int l = l0 + r;
            float a = 0.f;
            if (l < L) {
                size_t off = ((size_t)b * L + l) * S + s0 + c;
                float sv = alpha[off];
                a = __expf(sv - Ms[r]) * Zs[r];
                alpha[off] = a;
            }
            As[r][c] = a;
        }
        // stage x chunk [SC x D] via float4
#pragma unroll
        for (int t = 0; t < 8; t++) {
            int idx4 = tid + t * 256;    // 0..2047 (32*64 float4)
            int r  = idx4 >> 6;
            int c4 = idx4 & 63;
            ((float4*)&Xs[r][0])[c4] =
                ((const float4*)(xb + (size_t)(s0 + r) * D))[c4];
        }
        __syncthreads();

#pragma unroll 4
        for (int ss = 0; ss < SC; ss++) {
            float av[4];
#pragma unroll
            for (int i = 0; i < 4; i++) av[i] = As[ty * 4 + i][ss];
            float4 x0 = *(const float4*)&Xs[ss][tx * 16];
            float4 x1 = *(const float4*)&Xs[ss][tx * 16 + 4];
            float4 x2 = *(const float4*)&Xs[ss][tx * 16 + 8];
            float4 x3 = *(const float4*)&Xs[ss][tx * 16 + 12];
            float xv[16] = {x0.x, x0.y, x0.z, x0.w, x1.x, x1.y, x1.z, x1.w,
                            x2.x, x2.y, x2.z, x2.w, x3.x, x3.y, x3.z, x3.w};
#pragma unroll
            for (int i = 0; i < 4; i++)
#pragma unroll
                for (int k = 0; k < 16; k++)
                    acc[i][k] = fmaf(av[i], xv[k], acc[i][k]);
        }
        __syncthreads();
    }

    // write out tile
#pragma unroll
    for (int i = 0; i < 4; i++) {
        int l = l0 + ty * 4 + i;
        if (l >= L) continue;
        float4* dst = (float4*)(out + ((size_t)b * L + l) * D + tx * 16);
        dst[0] = make_float4(acc[i][0],  acc[i][1],  acc[i][2],  acc[i][3]);
        dst[1] = make_float4(acc[i][4],  acc[i][5],  acc[i][6],  acc[i][7]);
        dst[2] = make_float4(acc[i][8],  acc[i][9],  acc[i][10], acc[i][11]);
        dst[3] = make_float4(acc[i][12], acc[i][13], acc[i][14], acc[i][15]);
    }
}

// ---------------------------------------------------------------------------
extern "C" void kernel_launch(void* const* d_in, const int* in_sizes, int n_in,
                              void* d_out, int out_size)
{
    const float* x = (const float*)d_in[0];   // [B,S,D]
    const float* U = (const float*)d_in[1];   // [L,D]

    float* out_ptr   = (float*)d_out;                      // [B,L,D]
    float* alpha_ptr = (float*)d_out + (size_t)B * L * D;  // [B,L,S]

    // K1: raw scores + partial stats
    dim3 g1(NST, NLT, B);
    k_scores<<<g1, 256>>>(x, U, alpha_ptr);

    // K2: reduce stats
    int n = B * L;
    k_reduce<<<(n + 255) / 256, 256>>>();

    // K3: normalize alpha in place + out GEMM
    dim3 g3(NLT3, B);
    k_out<<<g3, 256>>>(x, alpha_ptr, out_ptr);
}

// round 2
// speedup vs baseline: 1.9827x; 1.9827x over previous
#include <cuda_runtime.h>
#include <cuda_bf16.h>
#include <mma.h>
#include <cstdint>

using namespace nvcuda;

// Problem constants
constexpr int B = 4;
constexpr int S = 4096;
constexpr int D = 256;
constexpr int L = 8921;

// K1 tiling
constexpr int LT1 = 128;
constexpr int ST1 = 128;
constexpr int KC1 = 32;                    // k-chunk
constexpr int NLT = (L + LT1 - 1) / LT1;   // 70
constexpr int NST = S / ST1;               // 32
constexpr int LDA1 = KC1 + 8;              // 40 halves, padded

// K3 tiling
constexpr int LT3 = 128;
constexpr int SC3 = 32;                    // k(=s)-chunk
constexpr int NLT3 = (L + LT3 - 1) / LT3;  // 70
constexpr int LDA3 = SC3 + 8;              // 40
constexpr int LDX3 = D + 8;                // 264

// Scratch (no cudaMalloc allowed)
__device__ float g_pm[(size_t)B * L * NST];
__device__ float g_pz[(size_t)B * L * NST];
__device__ float g_M [(size_t)B * L];
__device__ float g_Zi[(size_t)B * L];

__device__ __forceinline__ void split_bf16(float v, __nv_bfloat16& h, __nv_bfloat16& l)
{
    h = __float2bfloat16(v);                       // RN
    l = __float2bfloat16(v - __bfloat162float(h)); // exact residual, then RN
}

// ---------------------------------------------------------------------------
// K1: scores[b,l,s] = sum_d U[l,d]*x[b,s,d] via bf16 3-term wmma.
//     Writes raw scores into alpha buffer + per-(l, s-tile) partial stats.
// ---------------------------------------------------------------------------
__global__ void __launch_bounds__(256) k_scores(
    const float* __restrict__ x, const float* __restrict__ U,
    float* __restrict__ sc)
{
    extern __shared__ char smem[];
    __nv_bfloat16* Uh = (__nv_bfloat16*)smem;                 // [128][LDA1]
    __nv_bfloat16* Ul = Uh + LT1 * LDA1;
    __nv_bfloat16* Xh = Ul + LT1 * LDA1;
    __nv_bfloat16* Xl = Xh + ST1 * LDA1;

    const int b  = blockIdx.z;
    const int lt = blockIdx.y;
    const int st = blockIdx.x;
    const int l0 = lt * LT1;
    const int s0 = st * ST1;

    const int tid  = threadIdx.x;
    const int warp = tid >> 5;
    const int lane = tid & 31;
    const int wm = warp >> 1;   // 0..3 : 32 l-rows each
    const int wn = warp & 1;    // 0..1 : 64 s-cols each

    wmma::fragment<wmma::accumulator, 16, 16, 16, float> acc[2][4];
#pragma unroll
    for (int i = 0; i < 2; i++)
#pragma unroll
        for (int j = 0; j < 4; j++) wmma::fill_fragment(acc[i][j], 0.f);

    const float* xb = x + (size_t)b * S * D;

    for (int kc = 0; kc < D; kc += KC1) {
        // stage + split: 128x32 of U and x each (4096 elems, 16/thread)
#pragma unroll
        for (int t = 0; t < 16; t++) {
            int idx = t * 256 + tid;
            int r = idx >> 5;
            int c = idx & 31;
            float uv = (l0 + r < L) ? U[(size_t)(l0 + r) * D + kc + c] : 0.f;
            split_bf16(uv, Uh[r * LDA1 + c], Ul[r * LDA1 + c]);
            float xv = xb[(size_t)(s0 + r) * D + kc + c];
            split_bf16(xv, Xh[r * LDA1 + c], Xl[r * LDA1 + c]);
        }
        __syncthreads();

#pragma unroll
        for (int ks = 0; ks < 2; ks++) {
            wmma::fragment<wmma::matrix_a, 16, 16, 16, __nv_bfloat16, wmma::row_major> ah[2], al[2];
#pragma unroll
            for (int i = 0; i < 2; i++) {
                const int ro = (wm * 32 + i * 16) * LDA1 + ks * 16;
                wmma::load_matrix_sync(ah[i], Uh + ro, LDA1);
                wmma::load_matrix_sync(al[i], Ul + ro, LDA1);
            }
#pragma unroll
            for (int j = 0; j < 4; j++) {
                wmma::fragment<wmma::matrix_b, 16, 16, 16, __nv_bfloat16, wmma::col_major> bh, bl;
                const int co = (wn * 64 + j * 16) * LDA1 + ks * 16;
                wmma::load_matrix_sync(bh, Xh + co, LDA1);
                wmma::load_matrix_sync(bl, Xl + co, LDA1);
#pragma unroll
                for (int i = 0; i < 2; i++) {
                    wmma::mma_sync(acc[i][j], ah[i], bh, acc[i][j]);
                    wmma::mma_sync(acc[i][j], ah[i], bl, acc[i][j]);
                    wmma::mma_sync(acc[i][j], al[i], bh, acc[i][j]);
                }
            }
        }
        __syncthreads();
    }

    // Epilogue: stage C in SMEM (reuses operand space), compute row stats, store.
    float* Cs = (float*)smem;   // [128][132]
    const int ldC = 132;
#pragma unroll
    for (int i = 0; i < 2; i++)
#pragma unroll
        for (int j = 0; j < 4; j++)
            wmma::store_matrix_sync(Cs + (size_t)(wm * 32 + i * 16) * ldC + wn * 64 + j * 16,
                                    acc[i][j], ldC, wmma::mem_row_major);
    __syncthreads();

#pragma unroll
    for (int r = 0; r < 16; r++) {
        int row = warp * 16 + r;
        int l = l0 + row;
        float4 v = *(const float4*)&Cs[row * ldC + lane * 4];

        float m = fmaxf(fmaxf(v.x, v.y), fmaxf(v.z, v.w));
#pragma unroll
        for (int o = 16; o > 0; o >>= 1)
            m = fmaxf(m, __shfl_xor_sync(0xffffffffu, m, o));

        float z = __expf(v.x - m) + __expf(v.y - m) + __expf(v.z - m) + __expf(v.w - m);
#pragma unroll
        for (int o = 16; o > 0; o >>= 1)
            z += __shfl_xor_sync(0xffffffffu, z, o);

        if (l < L) {
            *(float4*)(sc + ((size_t)b * L + l) * S + s0 + lane * 4) = v;
            if (lane == 0) {
                size_t pidx = ((size_t)b * L + l) * NST + st;
                g_pm[pidx] = m;
                g_pz[pidx] = z;
            }
        }
    }
}

// ---------------------------------------------------------------------------
// K2: reduce partial stats -> global max M and 1/Z
// ---------------------------------------------------------------------------
__global__ void k_reduce()
{
    int idx = blockIdx.x * blockDim.x + threadIdx.x;
    if (idx >= B * L) return;
    const float* pm = g_pm + (size_t)idx * NST;
    const float* pz = g_pz + (size_t)idx * NST;
    float M = -3.4e38f;
#pragma unroll
    for (int t = 0; t < NST; t++) M = fmaxf(M, pm[t]);
    float Z = 0.f;
#pragma unroll
    for (int t = 0; t < NST; t++) Z += pz[t] * __expf(pm[t] - M);
    g_M[idx]  = M;
    g_Zi[idx] = 1.0f / Z;
}

// ---------------------------------------------------------------------------
// K3: alpha = exp(score - M)*Zi in place; out = alpha @ x via bf16 3-term wmma
// ---------------------------------------------------------------------------
__global__ void __launch_bounds__(256, 1) k_out(
    const float* __restrict__ x,
    float* __restrict__ alpha,
    float* __restrict__ out)
{
    extern __shared__ char smem[];
    __nv_bfloat16* Ah = (__nv_bfloat16*)smem;                 // [128][LDA3]
    __nv_bfloat16* Al = Ah + LT3 * LDA3;
    __nv_bfloat16* Xh = Al + LT3 * LDA3;                      // [32][LDX3]
    __nv_bfloat16* Xl = Xh + SC3 * LDX3;
    float* Ms = (float*)(Xl + SC3 * LDX3);                    // [128]
    float* Zs = Ms + LT3;                                     // [128]

    const int b  = blockIdx.y;
    const int lt = blockIdx.x;
    const int l0 = lt * LT3;

    const int tid  = threadIdx.x;
    const int warp = tid >> 5;
    const int lane = tid & 31;
    const int wm = warp >> 1;   // 0..3 : 32 l-rows
    const int wn = warp & 1;    // 0..1 : 128 d-cols

    if (tid < LT3) {
        int l = l0 + tid;
        bool v = (l < L);
        Ms[tid] = v ? g_M [(size_t)b * L + l] : 0.f;
        Zs[tid] = v ? g_Zi[(size_t)b * L + l] : 0.f;
    }
    __syncthreads();

    wmma::fragment<wmma::accumulator, 16, 16, 16, float> acc[2][8];
#pragma unroll
    for (int i = 0; i < 2; i++)
#pragma unroll
        for (int j = 0; j < 8; j++) wmma::fill_fragment(acc[i][j], 0.f);

    const float* xb = x + (size_t)b * S * D;

    for (int s0 = 0; s0 < S; s0 += SC3) {
        // scores -> alpha (in place) + split into SMEM [128][32]
#pragma unroll
        for (int t = 0; t < 16; t++) {
            int idx = t * 256 + tid;
            int r = idx >> 5;
            int c = idx & 31;
            int l = l0 + r;
            float a = 0.f;
            if (l < L) {
                size_t off = ((size_t)b * L + l) * S + s0 + c;
                float sv = alpha[off];
                a = __expf(sv - Ms[r]) * Zs[r];
                alpha[off] = a;
            }
            split_bf16(a, Ah[r * LDA3 + c], Al[r * LDA3 + c]);
        }
        // x chunk [32][256], float4 loads (2048 float4, 8/thread)
#pragma unroll
        for (int t = 0; t < 8; t++) {
            int idx4 = t * 256 + tid;
            int r  = idx4 >> 6;
            int c4 = idx4 & 63;
            float4 xv = ((const float4*)(xb + (size_t)(s0 + r) * D))[c4];
            int o = r * LDX3 + c4 * 4;
            split_bf16(xv.x, Xh[o + 0], Xl[o + 0]);
            split_bf16(xv.y, Xh[o + 1], Xl[o + 1]);
            split_bf16(xv.z, Xh[o + 2], Xl[o + 2]);
            split_bf16(xv.w, Xh[o + 3], Xl[o + 3]);
        }
        __syncthreads();

#pragma unroll
        for (int ks = 0; ks < 2; ks++) {
            wmma::fragment<wmma::matrix_a, 16, 16, 16, __nv_bfloat16, wmma::row_major> ah[2], al[2];
#pragma unroll
            for (int i = 0; i < 2; i++) {
                const int ro = (wm * 32 + i * 16) * LDA3 + ks * 16;
                wmma::load_matrix_sync(ah[i], Ah + ro, LDA3);
                wmma::load_matrix_sync(al[i], Al + ro, LDA3);
            }
#pragma unroll
            for (int j = 0; j < 8; j++) {
                wmma::fragment<wmma::matrix_b, 16, 16, 16, __nv_bfloat16, wmma::row_major> bh, bl;
                const int co = (ks * 16) * LDX3 + wn * 128 + j * 16;
                wmma::load_matrix_sync(bh, Xh + co, LDX3);
                wmma::load_matrix_sync(bl, Xl + co, LDX3);
#pragma unroll
                for (int i = 0; i < 2; i++) {
                    wmma::mma_sync(acc[i][j], ah[i], bh, acc[i][j]);
                    wmma::mma_sync(acc[i][j], ah[i], bl, acc[i][j]);
                    wmma::mma_sync(acc[i][j], al[i], bh, acc[i][j]);
                }
            }
        }
        __syncthreads();
    }

    // Epilogue
    if (l0 + LT3 <= L) {
        // fast path: direct fragment stores to gmem
#pragma unroll
        for (int i = 0; i < 2; i++)
#pragma unroll
            for (int j = 0; j < 8; j++)
                wmma::store_matrix_sync(
                    out + ((size_t)b * L + l0 + wm * 32 + i * 16) * D + wn * 128 + j * 16,
                    acc[i][j], D, wmma::mem_row_major);
    } else {
        // boundary tile: stage per-warp, guarded copy
        float* buf = (float*)smem + (size_t)warp * (16 * 136);
#pragma unroll
        for (int i = 0; i < 2; i++) {
#pragma unroll
            for (int j = 0; j < 8; j++)
                wmma::store_matrix_sync(buf + j * 16, acc[i][j], 136, wmma::mem_row_major);
            __syncwarp();
#pragma unroll
            for (int r = 0; r < 16; r++) {
                int l = l0 + wm * 32 + i * 16 + r;
                if (l < L)
                    *(float4*)(out + ((size_t)b * L + l) * D + wn * 128 + lane * 4) =
                        *(const float4*)&buf[r * 136 + lane * 4];
            }
            __syncwarp();
        }
    }
}

// ---------------------------------------------------------------------------
extern "C" void kernel_launch(void* const* d_in, const int* in_sizes, int n_in,
                              void* d_out, int out_size)
{
    const float* x = (const float*)d_in[0];   // [B,S,D]
    const float* U = (const float*)d_in[1];   // [L,D]

    float* out_ptr   = (float*)d_out;                      // [B,L,D]
    float* alpha_ptr = (float*)d_out + (size_t)B * L * D;  // [B,L,S]

    // dynamic SMEM sizes
    const int smem1 = 128 * 132 * 4;                             // 67584 (>= operand stage)
    const int smem3 = 8 * 16 * 136 * 4;                          // 69632 (>= operand stage)

    cudaFuncSetAttribute(k_scores, cudaFuncAttributeMaxDynamicSharedMemorySize, smem1);
    cudaFuncSetAttribute(k_out,    cudaFuncAttributeMaxDynamicSharedMemorySize, smem3);

    dim3 g1(NST, NLT, B);
    k_scores<<<g1, 256, smem1>>>(x, U, alpha_ptr);

    int n = B * L;
    k_reduce<<<(n + 255) / 256, 256>>>();

    dim3 g3(NLT3, B);
    k_out<<<g3, 256, smem3>>>(x, alpha_ptr, out_ptr);
}

// round 6
// speedup vs baseline: 5.7920x; 2.9212x over previous
#include <cuda_runtime.h>
#include <cuda_bf16.h>
#include <cstdint>

constexpr int B = 4;
constexpr int S = 4096;
constexpr int D = 256;
constexpr int L = 8921;

constexpr int NST = 16;     // S/256 s-tiles in K1
constexpr int NLT = 70;     // ceil(L/128)

// ---------------- device scratch ------------------------------------------
__device__ float g_pm[(size_t)B * L * NST];
__device__ float g_pz[(size_t)B * L * NST];
__device__ float g_M [(size_t)B * L];
__device__ float g_Zi[(size_t)B * L];

__device__ __nv_bfloat16 gUh[(size_t)L * D];
__device__ __nv_bfloat16 gUl[(size_t)L * D];
__device__ __nv_bfloat16 gXh[(size_t)B * S * D];
__device__ __nv_bfloat16 gXl[(size_t)B * S * D];
__device__ __nv_bfloat16 gTh[(size_t)B * D * S];   // x transposed: [b][d][s]
__device__ __nv_bfloat16 gTl[(size_t)B * D * S];

// ---------------- helpers --------------------------------------------------
__device__ __forceinline__ uint32_t smem_u32(const void* p) {
    uint32_t a;
    asm("{ .reg .u64 t; cvta.to.shared.u64 t, %1; cvt.u32.u64 %0, t; }" : "=r"(a) : "l"(p));
    return a;
}
__device__ __forceinline__ void cp16(uint32_t d, const void* s, uint32_t sz) {
    asm volatile("cp.async.cg.shared.global [%0], [%1], 16, %2;"
                 :: "r"(d), "l"(s), "r"(sz) : "memory");
}
__device__ __forceinline__ void cp_commit() {
    asm volatile("cp.async.commit_group;" ::: "memory");
}
template<int N> __device__ __forceinline__ void cp_wait() {
    asm volatile("cp.async.wait_group %0;" :: "n"(N) : "memory");
}
__device__ __forceinline__ void ldsm4(uint32_t* r, uint32_t a) {
    asm volatile("ldmatrix.sync.aligned.m8n8.x4.shared.b16 {%0,%1,%2,%3}, [%4];"
                 : "=r"(r[0]), "=r"(r[1]), "=r"(r[2]), "=r"(r[3]) : "r"(a));
}
__device__ __forceinline__ void mma_bf16(float* d, const uint32_t* a, uint32_t b0, uint32_t b1) {
    asm volatile("mma.sync.aligned.m16n8k16.row.col.f32.bf16.bf16.f32 "
                 "{%0,%1,%2,%3}, {%4,%5,%6,%7}, {%8,%9}, {%0,%1,%2,%3};"
                 : "+f"(d[0]), "+f"(d[1]), "+f"(d[2]), "+f"(d[3])
                 : "r"(a[0]), "r"(a[1]), "r"(a[2]), "r"(a[3]), "r"(b0), "r"(b1));
}
__device__ __forceinline__ void split1(float v, __nv_bfloat16& h, __nv_bfloat16& l) {
    h = __float2bfloat16(v);
    l = __float2bfloat16(v - __bfloat162float(h));
}
__device__ __forceinline__ uint32_t pack2(__nv_bfloat16 a, __nv_bfloat16 b) {
    __nv_bfloat162 t = __halves2bfloat162(a, b);
    return *reinterpret_cast<uint32_t*>(&t);
}

// ---------------- smem layout ----------------------------------------------
// rows padded to 80B (40 bf16): conflict-free ldmatrix, 16B-aligned cp.async
constexpr int HDR    = 6144;
constexpr int ST_AH  = 0;          // A hi: 128 rows * 80B
constexpr int ST_AL  = 10240;      // A lo
constexpr int ST_BH  = 20480;      // B hi: 256 rows * 80B
constexpr int ST_BL  = 40960;      // B lo
constexpr int STAGE  = 61440;
constexpr int SMEM_SZ = HDR + 3 * STAGE;   // 190464

// ---------------- precompute kernels ---------------------------------------
__global__ void k_split_u(const float* __restrict__ src) {
    int i = blockIdx.x * blockDim.x + threadIdx.x;
    if (i >= L * D / 4) return;
    float4 v = ((const float4*)src)[i];
    __nv_bfloat16 h0,h1,h2,h3,l0,l1,l2,l3;
    split1(v.x,h0,l0); split1(v.y,h1,l1); split1(v.z,h2,l2); split1(v.w,h3,l3);
    ((uint2*)gUh)[i] = make_uint2(pack2(h0,h1), pack2(h2,h3));
    ((uint2*)gUl)[i] = make_uint2(pack2(l0,l1), pack2(l2,l3));
}
__global__ void k_split_x(const float* __restrict__ src) {
    int i = blockIdx.x * blockDim.x + threadIdx.x;
    if (i >= B * S * D / 4) return;
    float4 v = ((const float4*)src)[i];
    __nv_bfloat16 h0,h1,h2,h3,l0,l1,l2,l3;
    split1(v.x,h0,l0); split1(v.y,h1,l1); split1(v.z,h2,l2); split1(v.w,h3,l3);
    ((uint2*)gXh)[i] = make_uint2(pack2(h0,h1), pack2(h2,h3));
    ((uint2*)gXl)[i] = make_uint2(pack2(l0,l1), pack2(l2,l3));
}
__global__ void k_tsplit(const float* __restrict__ x) {
    __shared__ float t[32][33];
    int b = blockIdx.z, s0 = blockIdx.x * 32, d0 = blockIdx.y * 32;
    int tx = threadIdx.x, ty = threadIdx.y;
    const float* xb = x + (size_t)b * S * D;
#pragma unroll
    for (int i = 0; i < 32; i += 8)
        t[ty + i][tx] = xb[(size_t)(s0 + ty + i) * D + d0 + tx];
    __syncthreads();
#pragma unroll
    for (int i = 0; i < 32; i += 8) {
        int dr = ty + i;
        float v = t[tx][dr];
        __nv_bfloat16 h, l; split1(v, h, l);
        size_t o = ((size_t)b * D + d0 + dr) * S + s0 + tx;
        gTh[o] = h; gTl[o] = l;
    }
}

// ---------------- shared MMA tile body --------------------------------------
// warp tile 32(m) x 64(n), k-chunk 32; acc[2 mt][8 nt][4]
struct MmaCtx {
    uint32_t arow;   // A ldmatrix per-lane base offset within stage
    uint32_t brow;   // B ldmatrix per-lane base offset within stage
};

__device__ __forceinline__ void tile_mma(uint32_t base, const MmaCtx& cx,
                                         float (&acc)[2][8][4])
{
#pragma unroll
    for (int ks = 0; ks < 2; ks++) {
        uint32_t Ah[2][4], Al[2][4];
#pragma unroll
        for (int mt = 0; mt < 2; mt++) {
            ldsm4(Ah[mt], base + ST_AH + cx.arow + mt * 1280 + ks * 32);
            ldsm4(Al[mt], base + ST_AL + cx.arow + mt * 1280 + ks * 32);
        }
#pragma unroll
        for (int np = 0; np < 4; np++) {
            uint32_t Bh[4], Bl[4];
            ldsm4(Bh, base + ST_BH + cx.brow + np * 1280 + ks * 32);
            ldsm4(Bl, base + ST_BL + cx.brow + np * 1280 + ks * 32);
#pragma unroll
            for (int mt = 0; mt < 2; mt++) {
                mma_bf16(acc[mt][np*2],   Ah[mt], Bh[0], Bh[1]);
                mma_bf16(acc[mt][np*2+1], Ah[mt], Bh[2], Bh[3]);
                mma_bf16(acc[mt][np*2],   Ah[mt], Bl[0], Bl[1]);
                mma_bf16(acc[mt][np*2+1], Ah[mt], Bl[2], Bl[3]);
                mma_bf16(acc[mt][np*2],   Al[mt], Bh[0], Bh[1]);
                mma_bf16(acc[mt][np*2+1], Al[mt], Bh[2], Bh[3]);
            }
        }
    }
}

__device__ __forceinline__ MmaCtx make_ctx(int warp, int lane) {
    int wm = warp & 3, wn = warp >> 2;
    MmaCtx c;
    c.arow = (uint32_t)((wm * 32 + (lane & 15)) * 80 + (lane >> 4) * 16);
    c.brow = (uint32_t)((wn * 64 + (lane & 7) + ((lane >> 4) & 1) * 8) * 80
                        + ((lane >> 3) & 1) * 16);
    return c;
}

// ---------------- K1: scores + per-tile softmax stats -----------------------
__global__ void __launch_bounds__(512) k1(float* __restrict__ sc)
{
    extern __shared__ __align__(128) char smem[];
    const uint32_t sb = smem_u32(smem);
    const int tid = threadIdx.x, lane = tid & 31, warp = tid >> 5;
    const int wm = warp & 3, wn = warp >> 2;
    const int bb = blockIdx.z, lt = blockIdx.y, st = blockIdx.x;
    const int l0 = lt * 128, s0 = st * 256;
    const MmaCtx cx = make_ctx(warp, lane);

    float acc[2][8][4];
#pragma unroll
    for (int i = 0; i < 2; i++)
#pragma unroll
        for (int j = 0; j < 8; j++)
#pragma unroll
            for (int k = 0; k < 4; k++) acc[i][j][k] = 0.f;

    // ---- cp.async staging for chunk c (kc = c*32) ----
    auto stage_c = [&](int c) {
        uint32_t base = sb + HDR + (c % 3) * STAGE;
        int kc = c * 32;
        {   // A: 128 rows x 64B, 512 x 16B per matrix -> 1 per thread each
            int r = tid >> 2, c16 = tid & 3;
            int l = l0 + r;
            int lc = l < L ? l : L - 1;
            uint32_t sz = (l < L) ? 16u : 0u;
            size_t g = (size_t)lc * D + kc + c16 * 8;
            uint32_t so = r * 80 + c16 * 16;
            cp16(base + ST_AH + so, gUh + g, sz);
            cp16(base + ST_AL + so, gUl + g, sz);
        }
#pragma unroll
        for (int t = 0; t < 2; t++) {   // B: 256 rows -> 1024 x 16B per matrix
            int idx = t * 512 + tid;
            int r = idx >> 2, c16 = idx & 3;
            size_t g = ((size_t)bb * S + s0 + r) * D + kc + c16 * 8;
            uint32_t so = r * 80 + c16 * 16;
            cp16(base + ST_BH + so, gXh + g, 16);
            cp16(base + ST_BL + so, gXl + g, 16);
        }
        cp_commit();
    };

    stage_c(0);
    stage_c(1);

    constexpr int NC = 8;
    for (int c = 0; c < NC; c++) {
        if (c < NC - 1) cp_wait<1>(); else cp_wait<0>();
        __syncthreads();
        if (c + 2 < NC) stage_c(c + 2);
        tile_mma(sb + HDR + (c % 3) * STAGE, cx, acc);
    }

    // ---- epilogue: stats + score stores ----
    float* spmax = (float*)smem;          // [4][128]
    float* spz   = spmax + 512;           // [4][128]
    float* srow  = spz + 512;             // [128]
    const int rbase = wm * 32 + (lane >> 2);

    // per-row max across this warp's 64 cols
#pragma unroll
    for (int mt = 0; mt < 2; mt++)
#pragma unroll
        for (int h = 0; h < 2; h++) {
            float m = -3.4e38f;
#pragma unroll
            for (int nt = 0; nt < 8; nt++)
                m = fmaxf(m, fmaxf(acc[mt][nt][h*2], acc[mt][nt][h*2+1]));
            m = fmaxf(m, __shfl_xor_sync(0xffffffffu, m, 1));
            m = fmaxf(m, __shfl_xor_sync(0xffffffffu, m, 2));
            if ((lane & 3) == 0)
                spmax[wn * 128 + rbase + mt * 16 + h * 8] = m;
        }
    __syncthreads();
    if (tid < 128) {
        float m = fmaxf(fmaxf(spmax[tid], spmax[128 + tid]),
                        fmaxf(spmax[256 + tid], spmax[384 + tid]));
        srow[tid] = m;
    }
    __syncthreads();
#pragma unroll
    for (int mt = 0; mt < 2; mt++)
#pragma unroll
        for (int h = 0; h < 2; h++) {
            float M = srow[rbase + mt * 16 + h * 8];
            float z = 0.f;
#pragma unroll
            for (int nt = 0; nt < 8; nt++)
                z += __expf(acc[mt][nt][h*2] - M) + __expf(acc[mt][nt][h*2+1] - M);
            z += __shfl_xor_sync(0xffffffffu, z, 1);
            z += __shfl_xor_sync(0xffffffffu, z, 2);
            if ((lane & 3) == 0)
                spz[wn * 128 + rbase + mt * 16 + h * 8] = z;
        }
    __syncthreads();
    if (tid < 128) {
        int l = l0 + tid;
        if (l < L) {
            size_t p = ((size_t)bb * L + l) * NST + st;
            g_pm[p] = srow[tid];
            g_pz[p] = spz[tid] + spz[128 + tid] + spz[256 + tid] + spz[384 + tid];
        }
    }

    // raw score stores
#pragma unroll
    for (int mt = 0; mt < 2; mt++) {
        int r0 = l0 + wm * 32 + mt * 16 + (lane >> 2);
#pragma unroll
        for (int nt = 0; nt < 8; nt++) {
            int col = s0 + wn * 64 + nt * 8 + (lane & 3) * 2;
            if (r0 < L)
                *(float2*)(sc + ((size_t)bb * L + r0) * S + col) =
                    make_float2(acc[mt][nt][0], acc[mt][nt][1]);
            if (r0 + 8 < L)
                *(float2*)(sc + ((size_t)bb * L + r0 + 8) * S + col) =
                    make_float2(acc[mt][nt][2], acc[mt][nt][3]);
        }
    }
}

// ---------------- K2: reduce partial stats ----------------------------------
__global__ void k_reduce() {
    int idx = blockIdx.x * blockDim.x + threadIdx.x;
    if (idx >= B * L) return;
    const float* pm = g_pm + (size_t)idx * NST;
    const float* pz = g_pz + (size_t)idx * NST;
    float M = -3.4e38f;
#pragma unroll
    for (int t = 0; t < NST; t++) M = fmaxf(M, pm[t]);
    float Z = 0.f;
#pragma unroll
    for (int t = 0; t < NST; t++) Z += pz[t] * __expf(pm[t] - M);
    g_M[idx]  = M;
    g_Zi[idx] = 1.0f / Z;
}

// ---------------- K3: alpha (final) + out = alpha @ x -----------------------
__global__ void __launch_bounds__(512) k3(float* __restrict__ alpha,
                                          float* __restrict__ out)
{
    extern __shared__ __align__(128) char smem[];
    const uint32_t sb = smem_u32(smem);
    const int tid = threadIdx.x, lane = tid & 31, warp = tid >> 5;
    const int wm = warp & 3, wn = warp >> 2;
    const int bb = blockIdx.y, lt = blockIdx.x, l0 = lt * 128;
    const MmaCtx cx = make_ctx(warp, lane);

    float* Ms = (float*)smem;         // [128]
    float* Zs = Ms + 128;             // [128]
    if (tid < 128) {
        int l = l0 + tid;
        Ms[tid] = (l < L) ? g_M [(size_t)bb * L + l] : 0.f;
        Zs[tid] = (l < L) ? g_Zi[(size_t)bb * L + l] : 0.f;
    }
    __syncthreads();

    float acc[2][8][4];
#pragma unroll
    for (int i = 0; i < 2; i++)
#pragma unroll
        for (int j = 0; j < 8; j++)
#pragma unroll
            for (int k = 0; k < 4; k++) acc[i][j][k] = 0.f;

    // per-thread A rows: idx = t*512+tid -> r = idx>>3, c4 = idx&7 (4 floats)
    const int ar0 = tid >> 3,        ac0 = tid & 7;
    const int ar1 = (512 + tid) >> 3, ac1 = (512 + tid) & 7;

    auto stage_b = [&](int c) {
        uint32_t base = sb + HDR + (c % 3) * STAGE;
        int s0 = c * 32;
#pragma unroll
        for (int t = 0; t < 2; t++) {
            int idx = t * 512 + tid;
            int r = idx >> 2, c16 = idx & 3;
            size_t g = ((size_t)bb * D + r) * S + s0 + c16 * 8;
            uint32_t so = r * 80 + c16 * 16;
            cp16(base + ST_BH + so, gTh + g, 16);
            cp16(base + ST_BL + so, gTl + g, 16);
        }
        cp_commit();
    };
    auto a_load = [&](int c, float4* v) {
        int s0 = c * 32;
        int l_0 = l0 + ar0, l_1 = l0 + ar1;
        v[0] = (l_0 < L) ? *(const float4*)(alpha + ((size_t)bb * L + l_0) * S + s0 + ac0 * 4)
                         : make_float4(0,0,0,0);
        v[1] = (l_1 < L) ? *(const float4*)(alpha + ((size_t)bb * L + l_1) * S + s0 + ac1 * 4)
                         : make_float4(0,0,0,0);
    };
    auto a_store = [&](int c, float4* v) {
        uint32_t base = sb + HDR + (c % 3) * STAGE;
        int s0 = c * 32;
#pragma unroll
        for (int t = 0; t < 2; t++) {
            int r  = t ? ar1 : ar0;
            int c4 = t ? ac1 : ac0;
            int l  = l0 + r;
            float4 a = v[t];
            float M = Ms[r], Z = Zs[r];
            a.x = __expf(a.x - M) * Z;
            a.y = __expf(a.y - M) * Z;
            a.z = __expf(a.z - M) * Z;
            a.w = __expf(a.w - M) * Z;
            if (l < L)
                *(float4*)(alpha + ((size_t)bb * L + l) * S + s0 + c4 * 4) = a;
            else
                a = make_float4(0,0,0,0);
            __nv_bfloat16 h0,h1,h2,h3,e0,e1,e2,e3;
            split1(a.x,h0,e0); split1(a.y,h1,e1); split1(a.z,h2,e2); split1(a.w,h3,e3);
            uint32_t so = r * 80 + c4 * 8;
            *(uint2*)(smem + HDR + (c % 3) * STAGE + ST_AH + so) =
                make_uint2(pack2(h0,h1), pack2(h2,h3));
            *(uint2*)(smem + HDR + (c % 3) * STAGE + ST_AL + so) =
                make_uint2(pack2(e0,e1), pack2(e2,e3));
            (void)base;
        }
    };

    // prologue
    float4 v0[2], v1[2];
    stage_b(0); a_load(0, v0); a_store(0, v0);
    stage_b(1); a_load(1, v1); a_store(1, v1);

    constexpr int NC = 128;
    float4 vp[2];
    for (int c = 0; c < NC; c++) {
        if (c < NC - 1) cp_wait<1>(); else cp_wait<0>();
        __syncthreads();
        bool pf = (c + 2 < NC);
        if (pf) { stage_b(c + 2); a_load(c + 2, vp); }
        tile_mma(sb + HDR + (c % 3) * STAGE, cx, acc);
        if (pf) a_store(c + 2, vp);
    }

    // epilogue: out stores
#pragma unroll
    for (int mt = 0; mt < 2; mt++) {
        int r0 = l0 + wm * 32 + mt * 16 + (lane >> 2);
#pragma unroll
        for (int nt = 0; nt < 8; nt++) {
            int col = wn * 64 + nt * 8 + (lane & 3) * 2;
            if (r0 < L)
                *(float2*)(out + ((size_t)bb * L + r0) * D + col) =
                    make_float2(acc[mt][nt][0], acc[mt][nt][1]);
            if (r0 + 8 < L)
                *(float2*)(out + ((size_t)bb * L + r0 + 8) * D + col) =
                    make_float2(acc[mt][nt][2], acc[mt][nt][3]);
        }
    }
}

// ---------------------------------------------------------------------------
extern "C" void kernel_launch(void* const* d_in, const int* in_sizes, int n_in,
                              void* d_out, int out_size)
{
    const float* x = (const float*)d_in[0];   // [B,S,D]
    const float* U = (const float*)d_in[1];   // [L,D]

    float* out_ptr   = (float*)d_out;                      // [B,L,D]
    float* alpha_ptr = (float*)d_out + (size_t)B * L * D;  // [B,L,S]

    cudaFuncSetAttribute(k1, cudaFuncAttributeMaxDynamicSharedMemorySize, SMEM_SZ);
    cudaFuncSetAttribute(k3, cudaFuncAttributeMaxDynamicSharedMemorySize, SMEM_SZ);

    k_split_u<<<(L * D / 4 + 255) / 256, 256>>>(U);
    k_split_x<<<(B * S * D / 4 + 255) / 256, 256>>>(x);
    k_tsplit<<<dim3(S / 32, D / 32, B), dim3(32, 8)>>>(x);

    k1<<<dim3(NST, NLT, B), 512, SMEM_SZ>>>(alpha_ptr);

    k_reduce<<<(B * L + 255) / 256, 256>>>();

    k3<<<dim3(NLT, B), 512, SMEM_SZ>>>(alpha_ptr, out_ptr);
}

// round 7
// speedup vs baseline: 5.7936x; 1.0003x over previous
#include <cuda_runtime.h>
#include <cuda_bf16.h>
#include <cstdint>

constexpr int B = 4;
constexpr int S = 4096;
constexpr int D = 256;
constexpr int L = 8921;

constexpr int NST = 16;     // S/256 s-tiles in K1
constexpr int NLT = 70;     // ceil(L/128)

// ---------------- device scratch ------------------------------------------
__device__ float g_pm[(size_t)B * L * NST];
__device__ float g_pz[(size_t)B * L * NST];
__device__ float g_M [(size_t)B * L];
__device__ float g_Zi[(size_t)B * L];

__device__ __nv_bfloat16 gUh[(size_t)L * D];
__device__ __nv_bfloat16 gUl[(size_t)L * D];
__device__ __nv_bfloat16 gXh[(size_t)B * S * D];
__device__ __nv_bfloat16 gXl[(size_t)B * S * D];
__device__ __nv_bfloat16 gTh[(size_t)B * D * S];   // x transposed: [b][d][s]
__device__ __nv_bfloat16 gTl[(size_t)B * D * S];

// ---------------- helpers --------------------------------------------------
__device__ __forceinline__ uint32_t smem_u32(const void* p) {
    uint32_t a;
    asm("{ .reg .u64 t; cvta.to.shared.u64 t, %1; cvt.u32.u64 %0, t; }" : "=r"(a) : "l"(p));
    return a;
}
__device__ __forceinline__ void cp16(uint32_t d, const void* s, uint32_t sz) {
    asm volatile("cp.async.cg.shared.global [%0], [%1], 16, %2;"
                 :: "r"(d), "l"(s), "r"(sz) : "memory");
}
__device__ __forceinline__ void cp_commit() {
    asm volatile("cp.async.commit_group;" ::: "memory");
}
template<int N> __device__ __forceinline__ void cp_wait() {
    asm volatile("cp.async.wait_group %0;" :: "n"(N) : "memory");
}
__device__ __forceinline__ void ldsm4(uint32_t* r, uint32_t a) {
    asm volatile("ldmatrix.sync.aligned.m8n8.x4.shared.b16 {%0,%1,%2,%3}, [%4];"
                 : "=r"(r[0]), "=r"(r[1]), "=r"(r[2]), "=r"(r[3]) : "r"(a));
}
__device__ __forceinline__ void mma_bf16(float* d, const uint32_t* a, uint32_t b0, uint32_t b1) {
    asm volatile("mma.sync.aligned.m16n8k16.row.col.f32.bf16.bf16.f32 "
                 "{%0,%1,%2,%3}, {%4,%5,%6,%7}, {%8,%9}, {%0,%1,%2,%3};"
                 : "+f"(d[0]), "+f"(d[1]), "+f"(d[2]), "+f"(d[3])
                 : "r"(a[0]), "r"(a[1]), "r"(a[2]), "r"(a[3]), "r"(b0), "r"(b1));
}
__device__ __forceinline__ void split1(float v, __nv_bfloat16& h, __nv_bfloat16& l) {
    h = __float2bfloat16(v);
    l = __float2bfloat16(v - __bfloat162float(h));
}
__device__ __forceinline__ uint32_t pack2(__nv_bfloat16 a, __nv_bfloat16 b) {
    __nv_bfloat162 t = __halves2bfloat162(a, b);
    return *reinterpret_cast<uint32_t*>(&t);
}

// ---------------- smem layout ----------------------------------------------
// rows padded to 80B (40 bf16): conflict-free ldmatrix, 16B-aligned cp.async
constexpr int HDR    = 6144;
constexpr int ST_AH  = 0;          // A hi: 128 rows * 80B
constexpr int ST_AL  = 10240;      // A lo
constexpr int ST_BH  = 20480;      // B hi: 256 rows * 80B
constexpr int ST_BL  = 40960;      // B lo
constexpr int STAGE  = 61440;
constexpr int SMEM_SZ = HDR + 3 * STAGE;   // 190464

constexpr int LDC = 264;           // fp32 C staging row stride (bank-shift 8/row)

// ---------------- precompute kernels ---------------------------------------
__global__ void k_split_u(const float* __restrict__ src) {
    int i = blockIdx.x * blockDim.x + threadIdx.x;
    if (i >= L * D / 4) return;
    float4 v = ((const float4*)src)[i];
    __nv_bfloat16 h0,h1,h2,h3,l0,l1,l2,l3;
    split1(v.x,h0,l0); split1(v.y,h1,l1); split1(v.z,h2,l2); split1(v.w,h3,l3);
    ((uint2*)gUh)[i] = make_uint2(pack2(h0,h1), pack2(h2,h3));
    ((uint2*)gUl)[i] = make_uint2(pack2(l0,l1), pack2(l2,l3));
}
// merged: one pass over x produces gXh/gXl (natural) and gTh/gTl (transposed)
__global__ void k_tsplit(const float* __restrict__ x) {
    __shared__ float t[32][33];
    int b = blockIdx.z, s0 = blockIdx.x * 32, d0 = blockIdx.y * 32;
    int tx = threadIdx.x, ty = threadIdx.y;
    const float* xb = x + (size_t)b * S * D;
#pragma unroll
    for (int i = 0; i < 32; i += 8) {
        float v = xb[(size_t)(s0 + ty + i) * D + d0 + tx];
        t[ty + i][tx] = v;
        __nv_bfloat16 h, l; split1(v, h, l);
        size_t o = ((size_t)b * S + s0 + ty + i) * D + d0 + tx;
        gXh[o] = h; gXl[o] = l;
    }
    __syncthreads();
#pragma unroll
    for (int i = 0; i < 32; i += 8) {
        int dr = ty + i;
        float v = t[tx][dr];
        __nv_bfloat16 h, l; split1(v, h, l);
        size_t o = ((size_t)b * D + d0 + dr) * S + s0 + tx;
        gTh[o] = h; gTl[o] = l;
    }
}

// ---------------- shared MMA tile body --------------------------------------
// warp tile 32(m) x 64(n), k-chunk 32; acc[2 mt][8 nt][4]
struct MmaCtx {
    uint32_t arow;
    uint32_t brow;
};

__device__ __forceinline__ void tile_mma(uint32_t base, const MmaCtx& cx,
                                         float (&acc)[2][8][4])
{
#pragma unroll
    for (int ks = 0; ks < 2; ks++) {
        uint32_t Ah[2][4], Al[2][4];
#pragma unroll
        for (int mt = 0; mt < 2; mt++) {
            ldsm4(Ah[mt], base + ST_AH + cx.arow + mt * 1280 + ks * 32);
            ldsm4(Al[mt], base + ST_AL + cx.arow + mt * 1280 + ks * 32);
        }
#pragma unroll
        for (int np = 0; np < 4; np++) {
            uint32_t Bh[4], Bl[4];
            ldsm4(Bh, base + ST_BH + cx.brow + np * 1280 + ks * 32);
            ldsm4(Bl, base + ST_BL + cx.brow + np * 1280 + ks * 32);
#pragma unroll
            for (int mt = 0; mt < 2; mt++) {
                mma_bf16(acc[mt][np*2],   Ah[mt], Bh[0], Bh[1]);
                mma_bf16(acc[mt][np*2+1], Ah[mt], Bh[2], Bh[3]);
                mma_bf16(acc[mt][np*2],   Ah[mt], Bl[0], Bl[1]);
                mma_bf16(acc[mt][np*2+1], Ah[mt], Bl[2], Bl[3]);
                mma_bf16(acc[mt][np*2],   Al[mt], Bh[0], Bh[1]);
                mma_bf16(acc[mt][np*2+1], Al[mt], Bh[2], Bh[3]);
            }
        }
    }
}

__device__ __forceinline__ MmaCtx make_ctx(int warp, int lane) {
    int wm = warp & 3, wn = warp >> 2;
    MmaCtx c;
    c.arow = (uint32_t)((wm * 32 + (lane & 15)) * 80 + (lane >> 4) * 16);
    c.brow = (uint32_t)((wn * 64 + (lane & 7) + ((lane >> 4) & 1) * 8) * 80
                        + ((lane >> 3) & 1) * 16);
    return c;
}

// ---------------- K1: scores + per-tile softmax stats -----------------------
__global__ void __launch_bounds__(512) k1(float* __restrict__ sc)
{
    extern __shared__ __align__(128) char smem[];
    const uint32_t sb = smem_u32(smem);
    const int tid = threadIdx.x, lane = tid & 31, warp = tid >> 5;
    const int wm = warp & 3, wn = warp >> 2;
    const int bb = blockIdx.z, lt = blockIdx.y, st = blockIdx.x;
    const int l0 = lt * 128, s0 = st * 256;
    const MmaCtx cx = make_ctx(warp, lane);

    float acc[2][8][4];
#pragma unroll
    for (int i = 0; i < 2; i++)
#pragma unroll
        for (int j = 0; j < 8; j++)
#pragma unroll
            for (int k = 0; k < 4; k++) acc[i][j][k] = 0.f;

    auto stage_c = [&](int c) {
        uint32_t base = sb + HDR + (c % 3) * STAGE;
        int kc = c * 32;
        {
            int r = tid >> 2, c16 = tid & 3;
            int l = l0 + r;
            int lc = l < L ? l : L - 1;
            uint32_t sz = (l < L) ? 16u : 0u;
            size_t g = (size_t)lc * D + kc + c16 * 8;
            uint32_t so = r * 80 + c16 * 16;
            cp16(base + ST_AH + so, gUh + g, sz);
            cp16(base + ST_AL + so, gUl + g, sz);
        }
#pragma unroll
        for (int t = 0; t < 2; t++) {
            int idx = t * 512 + tid;
            int r = idx >> 2, c16 = idx & 3;
            size_t g = ((size_t)bb * S + s0 + r) * D + kc + c16 * 8;
            uint32_t so = r * 80 + c16 * 16;
            cp16(base + ST_BH + so, gXh + g, 16);
            cp16(base + ST_BL + so, gXl + g, 16);
        }
        cp_commit();
    };

    stage_c(0);
    stage_c(1);

    constexpr int NC = 8;
    for (int c = 0; c < NC; c++) {
        if (c < NC - 1) cp_wait<1>(); else cp_wait<0>();
        __syncthreads();
        if (c + 2 < NC) stage_c(c + 2);
        tile_mma(sb + HDR + (c % 3) * STAGE, cx, acc);
    }

    // ---- epilogue ----
    float* spmax = (float*)smem;          // [4][128]
    float* spz   = spmax + 512;           // [4][128]
    float* srow  = spz + 512;             // [128]
    float* Cs    = (float*)(smem + HDR);  // [128][LDC]
    const int rbase = wm * 32 + (lane >> 2);

    // per-row max across this warp's 64 cols
#pragma unroll
    for (int mt = 0; mt < 2; mt++)
#pragma unroll
        for (int h = 0; h < 2; h++) {
            float m = -3.4e38f;
#pragma unroll
            for (int nt = 0; nt < 8; nt++)
                m = fmaxf(m, fmaxf(acc[mt][nt][h*2], acc[mt][nt][h*2+1]));
            m = fmaxf(m, __shfl_xor_sync(0xffffffffu, m, 1));
            m = fmaxf(m, __shfl_xor_sync(0xffffffffu, m, 2));
            if ((lane & 3) == 0)
                spmax[wn * 128 + rbase + mt * 16 + h * 8] = m;
        }
    __syncthreads();   // also: all mainloop smem reads complete
    if (tid < 128) {
        float m = fmaxf(fmaxf(spmax[tid], spmax[128 + tid]),
                        fmaxf(spmax[256 + tid], spmax[384 + tid]));
        srow[tid] = m;
    }
    __syncthreads();
    // z + stage C into smem (stage area free now)
#pragma unroll
    for (int mt = 0; mt < 2; mt++) {
        const int r = wm * 32 + mt * 16 + (lane >> 2);
        const int ccol = wn * 64 + (lane & 3) * 2;
#pragma unroll
        for (int h = 0; h < 2; h++) {
            float M = srow[rbase + mt * 16 + h * 8];
            float z = 0.f;
#pragma unroll
            for (int nt = 0; nt < 8; nt++)
                z += __expf(acc[mt][nt][h*2] - M) + __expf(acc[mt][nt][h*2+1] - M);
            z += __shfl_xor_sync(0xffffffffu, z, 1);
            z += __shfl_xor_sync(0xffffffffu, z, 2);
            if ((lane & 3) == 0)
                spz[wn * 128 + rbase + mt * 16 + h * 8] = z;
        }
#pragma unroll
        for (int nt = 0; nt < 8; nt++) {
            *(float2*)&Cs[(size_t)r * LDC + ccol + nt * 8] =
                make_float2(acc[mt][nt][0], acc[mt][nt][1]);
            *(float2*)&Cs[(size_t)(r + 8) * LDC + ccol + nt * 8] =
                make_float2(acc[mt][nt][2], acc[mt][nt][3]);
        }
    }
    __syncthreads();
    if (tid < 128) {
        int l = l0 + tid;
        if (l < L) {
            size_t p = ((size_t)bb * L + l) * NST + st;
            g_pm[p] = srow[tid];
            g_pz[p] = spz[tid] + spz[128 + tid] + spz[256 + tid] + spz[384 + tid];
        }
    }
    // coalesced score stores
#pragma unroll
    for (int t = 0; t < 16; t++) {
        int idx = t * 512 + tid;
        int row = idx >> 6, c4 = idx & 63;
        int l = l0 + row;
        if (l < L)
            *(float4*)(sc + ((size_t)bb * L + l) * S + s0 + c4 * 4) =
                *(const float4*)&Cs[(size_t)row * LDC + c4 * 4];
    }
}

// ---------------- K2: reduce partial stats ----------------------------------
__global__ void k_reduce() {
    int idx = blockIdx.x * blockDim.x + threadIdx.x;
    if (idx >= B * L) return;
    const float* pm = g_pm + (size_t)idx * NST;
    const float* pz = g_pz + (size_t)idx * NST;
    float M = -3.4e38f;
#pragma unroll
    for (int t = 0; t < NST; t++) M = fmaxf(M, pm[t]);
    float Z = 0.f;
#pragma unroll
    for (int t = 0; t < NST; t++) Z += pz[t] * __expf(pm[t] - M);
    g_M[idx]  = M;
    g_Zi[idx] = 1.0f / Z;
}

// ---------------- K3: alpha (final) + out = alpha @ x -----------------------
__global__ void __launch_bounds__(512) k3(float* __restrict__ alpha,
                                          float* __restrict__ out)
{
    extern __shared__ __align__(128) char smem[];
    const uint32_t sb = smem_u32(smem);
    const int tid = threadIdx.x, lane = tid & 31, warp = tid >> 5;
    const int wm = warp & 3, wn = warp >> 2;
    const int bb = blockIdx.y, lt = blockIdx.x, l0 = lt * 128;
    const MmaCtx cx = make_ctx(warp, lane);

    float* Ms = (float*)smem;         // [128]
    float* Zs = Ms + 128;             // [128]
    if (tid < 128) {
        int l = l0 + tid;
        Ms[tid] = (l < L) ? g_M [(size_t)bb * L + l] : 0.f;
        Zs[tid] = (l < L) ? g_Zi[(size_t)bb * L + l] : 0.f;
    }
    __syncthreads();

    float acc[2][8][4];
#pragma unroll
    for (int i = 0; i < 2; i++)
#pragma unroll
        for (int j = 0; j < 8; j++)
#pragma unroll
            for (int k = 0; k < 4; k++) acc[i][j][k] = 0.f;

    const int ar0 = tid >> 3,        ac0 = tid & 7;
    const int ar1 = (512 + tid) >> 3, ac1 = (512 + tid) & 7;

    auto stage_b = [&](int c) {
        uint32_t base = sb + HDR + (c % 3) * STAGE;
        int s0 = c * 32;
#pragma unroll
        for (int t = 0; t < 2; t++) {
            int idx = t * 512 + tid;
            int r = idx >> 2, c16 = idx & 3;
            size_t g = ((size_t)bb * D + r) * S + s0 + c16 * 8;
            uint32_t so = r * 80 + c16 * 16;
            cp16(base + ST_BH + so, gTh + g, 16);
            cp16(base + ST_BL + so, gTl + g, 16);
        }
        cp_commit();
    };
    auto a_load = [&](int c, float4* v) {
        int s0 = c * 32;
        int l_0 = l0 + ar0, l_1 = l0 + ar1;
        v[0] = (l_0 < L) ? *(const float4*)(alpha + ((size_t)bb * L + l_0) * S + s0 + ac0 * 4)
                         : make_float4(0,0,0,0);
        v[1] = (l_1 < L) ? *(const float4*)(alpha + ((size_t)bb * L + l_1) * S + s0 + ac1 * 4)
                         : make_float4(0,0,0,0);
    };
    auto a_store = [&](int c, float4* v) {
        int s0 = c * 32;
#pragma unroll
        for (int t = 0; t < 2; t++) {
            int r  = t ? ar1 : ar0;
            int c4 = t ? ac1 : ac0;
            int l  = l0 + r;
            float4 a = v[t];
            float M = Ms[r], Z = Zs[r];
            a.x = __expf(a.x - M) * Z;
            a.y = __expf(a.y - M) * Z;
            a.z = __expf(a.z - M) * Z;
            a.w = __expf(a.w - M) * Z;
            if (l < L)
                *(float4*)(alpha + ((size_t)bb * L + l) * S + s0 + c4 * 4) = a;
            else
                a = make_float4(0,0,0,0);
            __nv_bfloat16 h0,h1,h2,h3,e0,e1,e2,e3;
            split1(a.x,h0,e0); split1(a.y,h1,e1); split1(a.z,h2,e2); split1(a.w,h3,e3);
            uint32_t so = r * 80 + c4 * 8;
            *(uint2*)(smem + HDR + (c % 3) * STAGE + ST_AH + so) =
                make_uint2(pack2(h0,h1), pack2(h2,h3));
            *(uint2*)(smem + HDR + (c % 3) * STAGE + ST_AL + so) =
                make_uint2(pack2(e0,e1), pack2(e2,e3));
        }
    };

    float4 v0[2], v1[2];
    stage_b(0); a_load(0, v0); a_store(0, v0);
    stage_b(1); a_load(1, v1); a_store(1, v1);

    constexpr int NC = 128;
    float4 vp[2];
    for (int c = 0; c < NC; c++) {
        if (c < NC - 1) cp_wait<1>(); else cp_wait<0>();
        __syncthreads();
        bool pf = (c + 2 < NC);
        if (pf) { stage_b(c + 2); a_load(c + 2, vp); }
        tile_mma(sb + HDR + (c % 3) * STAGE, cx, acc);
        if (pf) a_store(c + 2, vp);
    }

    // ---- epilogue: stage C, coalesced out stores ----
    __syncthreads();
    float* Cs = (float*)(smem + HDR);  // [128][LDC]
#pragma unroll
    for (int mt = 0; mt < 2; mt++) {
        const int r = wm * 32 + mt * 16 + (lane >> 2);
        const int ccol = wn * 64 + (lane & 3) * 2;
#pragma unroll
        for (int nt = 0; nt < 8; nt++) {
            *(float2*)&Cs[(size_t)r * LDC + ccol + nt * 8] =
                make_float2(acc[mt][nt][0], acc[mt][nt][1]);
            *(float2*)&Cs[(size_t)(r + 8) * LDC + ccol + nt * 8] =
                make_float2(acc[mt][nt][2], acc[mt][nt][3]);
        }
    }
    __syncthreads();
#pragma unroll
    for (int t = 0; t < 16; t++) {
        int idx = t * 512 + tid;
        int row = idx >> 6, c4 = idx & 63;
        int l = l0 + row;
        if (l < L)
            *(float4*)(out + ((size_t)bb * L + l) * D + c4 * 4) =
                *(const float4*)&Cs[(size_t)row * LDC + c4 * 4];
    }
}

// ---------------------------------------------------------------------------
extern "C" void kernel_launch(void* const* d_in, const int* in_sizes, int n_in,
                              void* d_out, int out_size)
{
    const float* x = (const float*)d_in[0];   // [B,S,D]
    const float* U = (const float*)d_in[1];   // [L,D]

    float* out_ptr   = (float*)d_out;                      // [B,L,D]
    float* alpha_ptr = (float*)d_out + (size_t)B * L * D;  // [B,L,S]

    cudaFuncSetAttribute(k1, cudaFuncAttributeMaxDynamicSharedMemorySize, SMEM_SZ);
    cudaFuncSetAttribute(k3, cudaFuncAttributeMaxDynamicSharedMemorySize, SMEM_SZ);

    k_split_u<<<(L * D / 4 + 255) / 256, 256>>>(U);
    k_tsplit<<<dim3(S / 32, D / 32, B), dim3(32, 8)>>>(x);

    k1<<<dim3(NST, NLT, B), 512, SMEM_SZ>>>(alpha_ptr);

    k_reduce<<<(B * L + 255) / 256, 256>>>();

    k3<<<dim3(NLT, B), 512, SMEM_SZ>>>(alpha_ptr, out_ptr);
}